// round 17
// baseline (speedup 1.0000x reference)
#include <cuda_runtime.h>
#include <cuda_bf16.h>
#include <cstdint>

// Problem constants
#define B_  2
#define N_  4096
#define E_  256
#define H_  8
#define TAU_ 32
#define HD_ 32
#define M_TOT (B_ * N_)              // 8192
#define SCALE_ 0.17677669529663687f  // 1/sqrt(32)

// bf16-split inputs (filled by convert_kernel)
#define XT (3 * M_TOT * E_)
#define WT (E_ * E_)
__device__ __nv_bfloat16 g_xhi[XT], g_xlo[XT];
__device__ __nv_bfloat16 g_whi[WT], g_wlo[WT];

// bf16-split projected Q', K', V' (filled by proj_mma_kernel)
__device__ __nv_bfloat16 g_qh[M_TOT * E_], g_ql[M_TOT * E_];
__device__ __nv_bfloat16 g_kh[M_TOT * E_], g_kl[M_TOT * E_];
__device__ __nv_bfloat16 g_vh[M_TOT * E_], g_vl[M_TOT * E_];

// ===========================================================================
// Helpers (LDSM/HMMA fallback path; tcgen05 PTX rejected by this toolchain)
// ===========================================================================
__device__ __forceinline__ uint32_t smem_u32(const void* p) {
    uint32_t a;
    asm("{ .reg .u64 t; cvta.to.shared.u64 t, %1; cvt.u32.u64 %0, t; }"
        : "=r"(a) : "l"(p));
    return a;
}

#define LDSM_X4(r0, r1, r2, r3, addr) \
    asm volatile("ldmatrix.sync.aligned.m8n8.x4.shared.b16 {%0,%1,%2,%3}, [%4];" \
                 : "=r"(r0), "=r"(r1), "=r"(r2), "=r"(r3) : "r"(addr))

#define LDSM_X4_T(r0, r1, r2, r3, addr) \
    asm volatile("ldmatrix.sync.aligned.m8n8.x4.trans.shared.b16 {%0,%1,%2,%3}, [%4];" \
                 : "=r"(r0), "=r"(r1), "=r"(r2), "=r"(r3) : "r"(addr))

#define MMA_BF16(c, a, b) \
    asm volatile("mma.sync.aligned.m16n8k16.row.col.f32.bf16.bf16.f32 " \
                 "{%0,%1,%2,%3}, {%4,%5,%6,%7}, {%8,%9}, {%0,%1,%2,%3};" \
                 : "+f"((c)[0]), "+f"((c)[1]), "+f"((c)[2]), "+f"((c)[3]) \
                 : "r"((a)[0]), "r"((a)[1]), "r"((a)[2]), "r"((a)[3]), \
                   "r"((b)[0]), "r"((b)[1]))

#define CP_ASYNC16(dst, src) \
    asm volatile("cp.async.ca.shared.global [%0], [%1], 16;" \
                 :: "r"(dst), "l"(src) : "memory")
#define CP_COMMIT()  asm volatile("cp.async.commit_group;" ::: "memory")
#define CP_WAIT0()   asm volatile("cp.async.wait_group 0;" ::: "memory")

__device__ __forceinline__ uint32_t pack_bf2(__nv_bfloat16 a, __nv_bfloat16 b) {
    __nv_bfloat162 t = __halves2bfloat162(a, b);
    return *reinterpret_cast<uint32_t*>(&t);
}

// Split two floats into packed bf16 (hi) and packed residual (lo)
__device__ __forceinline__ void split2(float x, float y, uint32_t& hi, uint32_t& lo) {
    __nv_bfloat16 hx = __float2bfloat16_rn(x);
    __nv_bfloat16 hy = __float2bfloat16_rn(y);
    __nv_bfloat16 lx = __float2bfloat16_rn(x - __bfloat162float(hx));
    __nv_bfloat16 ly = __float2bfloat16_rn(y - __bfloat162float(hy));
    hi = pack_bf2(hx, hy);
    lo = pack_bf2(lx, ly);
}

// ===========================================================================
// Kernel 0: fp32 -> bf16 hi/lo split of X (q,k,v) and W  (unchanged)
// ===========================================================================
__global__ void convert_kernel(const float* __restrict__ q, const float* __restrict__ k,
                               const float* __restrict__ v, const float* __restrict__ w)
{
    const int i4 = blockIdx.x * blockDim.x + threadIdx.x;
    const int R4 = M_TOT * E_ / 4;  // float4s per matrix
    const int X4 = 3 * R4;
    const int W4 = WT / 4;

    float4 val;
    __nv_bfloat16 *dh, *dl;
    int gi;
    if (i4 < X4) {
        int reg = i4 / R4;
        int l   = i4 - reg * R4;
        const float* s = (reg == 0) ? q : (reg == 1) ? k : v;
        val = ((const float4*)s)[l];
        dh = g_xhi; dl = g_xlo; gi = i4 * 4;
    } else if (i4 < X4 + W4) {
        int l = i4 - X4;
        val = ((const float4*)w)[l];
        dh = g_whi; dl = g_wlo; gi = l * 4;
    } else {
        return;
    }
    uint32_t h0, l0, h1, l1;
    split2(val.x, val.y, h0, l0);
    split2(val.z, val.w, h1, l1);
    uint2 H = {h0, h1}, L = {l0, l1};
    *(uint2*)&dh[gi] = H;
    *(uint2*)&dl[gi] = L;
}

// ===========================================================================
// Kernel 1: projection GEMM, occupancy-tuned.
// Tile 128(M) x 64(N) x 64(K-chunk), double-buffered cp.async, no reg staging.
// grid = (4 n-tiles, 64 m-tiles, 3 matrices), 256 threads (8 warps: 4m x 2n),
// warp tile 32x32. 2 CTAs/SM (48KB x 2 buffers, <=128 regs).
// ===========================================================================
__device__ __forceinline__ uint32_t swz(int row, int kbyte) {
    return (uint32_t)(row * 128 + ((((kbyte >> 4)) ^ (row & 7)) << 4) + (kbyte & 15));
}

// Per-buffer layout (48 KB): A_HI 16K | A_LO 16K | B_HI 8K | B_LO 8K
#define PB_A_HI 0
#define PB_A_LO 16384
#define PB_B_HI 32768
#define PB_B_LO 40960
#define PB_SIZE 49152
#define PROJ_SMEM (2 * PB_SIZE)

__global__ __launch_bounds__(256, 2)
void proj_mma_kernel(const float* __restrict__ bias)
{
    extern __shared__ char smem[];
    const uint32_t sb = smem_u32(smem);
    const int tid = threadIdx.x;
    const int wid = tid >> 5, lane = tid & 31;
    const int wm = wid & 3;          // 4 x 32 rows
    const int wn = wid >> 2;         // 2 x 32 cols
    const int z = blockIdx.z;

    const __nv_bfloat16* Ah = g_xhi + (size_t)z * M_TOT * E_;
    const __nv_bfloat16* Al = g_xlo + (size_t)z * M_TOT * E_;
    __nv_bfloat16 *Oh, *Ol;
    if (z == 0)      { Oh = g_qh; Ol = g_ql; }
    else if (z == 1) { Oh = g_kh; Ol = g_kl; }
    else             { Oh = g_vh; Ol = g_vl; }

    const int rowA0 = blockIdx.y * 128;
    const int colB0 = blockIdx.x * 64;

    float acc[2][4][4];
    #pragma unroll
    for (int i = 0; i < 2; i++)
        #pragma unroll
        for (int j = 0; j < 4; j++)
            #pragma unroll
            for (int q = 0; q < 4; q++) acc[i][j][q] = 0.f;

    const int sub = lane >> 3, r8 = lane & 7;

    // Per-thread cp.async coordinates (fixed across chunks):
    // A: 1024 lines/array -> 4/thread: row = idx>>3 (0..127), gc = idx&7
    // B:  512 lines/array -> 2/thread: row = idx>>3 (0..63),  gc = idx&7
    const int a_row[4] = { (tid + 0) >> 3, (tid + 256) >> 3,
                           (tid + 512) >> 3, (tid + 768) >> 3 };
    const int a_gc  = tid & 7;
    const int b_row[2] = { (tid + 0) >> 3, (tid + 256) >> 3 };

    // issue chunk c into buffer buf
    auto issue = [&](int c, int buf) {
        const uint32_t bb = sb + buf * PB_SIZE;
        const int k0 = c * 64;
        #pragma unroll
        for (int i = 0; i < 4; i++) {
            uint32_t sw = swz(a_row[i], a_gc * 16);
            const __nv_bfloat16* srcH = &Ah[(rowA0 + a_row[i]) * E_ + k0 + a_gc * 8];
            const __nv_bfloat16* srcL = &Al[(rowA0 + a_row[i]) * E_ + k0 + a_gc * 8];
            CP_ASYNC16(bb + PB_A_HI + sw, srcH);
            CP_ASYNC16(bb + PB_A_LO + sw, srcL);
        }
        #pragma unroll
        for (int i = 0; i < 2; i++) {
            uint32_t sw = swz(b_row[i], a_gc * 16);
            const __nv_bfloat16* srcH = &g_whi[(colB0 + b_row[i]) * E_ + k0 + a_gc * 8];
            const __nv_bfloat16* srcL = &g_wlo[(colB0 + b_row[i]) * E_ + k0 + a_gc * 8];
            CP_ASYNC16(bb + PB_B_HI + sw, srcH);
            CP_ASYNC16(bb + PB_B_LO + sw, srcL);
        }
        CP_COMMIT();
    };

    issue(0, 0);

    for (int c = 0; c < 4; c++) {
        CP_WAIT0();
        __syncthreads();               // chunk c resident; prior MMAs done
        if (c < 3) issue(c + 1, (c + 1) & 1);

        const uint32_t bb = sb + (c & 1) * PB_SIZE;
        #pragma unroll
        for (int ks = 0; ks < 4; ks++) {
            uint32_t ahi[2][4], alo[2][4];
            #pragma unroll
            for (int mt = 0; mt < 2; mt++) {
                int arow = wm * 32 + mt * 16 + (sub & 1) * 8 + r8;
                int akb  = ks * 32 + (sub >> 1) * 16;
                uint32_t sw = swz(arow, akb);
                LDSM_X4(ahi[mt][0], ahi[mt][1], ahi[mt][2], ahi[mt][3],
                        bb + PB_A_HI + sw);
                LDSM_X4(alo[mt][0], alo[mt][1], alo[mt][2], alo[mt][3],
                        bb + PB_A_LO + sw);
            }
            uint32_t bhi[2][4], blo[2][4];
            #pragma unroll
            for (int np = 0; np < 2; np++) {
                int nrow = wn * 32 + np * 16 + (sub >> 1) * 8 + r8;
                int bkb  = ks * 32 + (sub & 1) * 16;
                uint32_t sw = swz(nrow, bkb);
                LDSM_X4(bhi[np][0], bhi[np][1], bhi[np][2], bhi[np][3],
                        bb + PB_B_HI + sw);
                LDSM_X4(blo[np][0], blo[np][1], blo[np][2], blo[np][3],
                        bb + PB_B_LO + sw);
            }
            #pragma unroll
            for (int mt = 0; mt < 2; mt++) {
                #pragma unroll
                for (int np = 0; np < 2; np++) {
                    MMA_BF16(acc[mt][np * 2 + 0], ahi[mt], &bhi[np][0]);
                    MMA_BF16(acc[mt][np * 2 + 1], ahi[mt], &bhi[np][2]);
                    MMA_BF16(acc[mt][np * 2 + 0], ahi[mt], &blo[np][0]);
                    MMA_BF16(acc[mt][np * 2 + 1], ahi[mt], &blo[np][2]);
                    MMA_BF16(acc[mt][np * 2 + 0], alo[mt], &bhi[np][0]);
                    MMA_BF16(acc[mt][np * 2 + 1], alo[mt], &bhi[np][2]);
                }
            }
        }
        __syncthreads();               // protect buffer before chunk c+2 lands
    }

    // Epilogue: add bias, split to bf16 hi/lo, store
    const int qrow = lane >> 2;
    const int qcol = (lane & 3) * 2;
    #pragma unroll
    for (int mt = 0; mt < 2; mt++) {
        int r = rowA0 + wm * 32 + mt * 16 + qrow;
        #pragma unroll
        for (int nt = 0; nt < 4; nt++) {
            int cb = colB0 + wn * 32 + nt * 8 + qcol;
            float b0 = bias[cb], b1 = bias[cb + 1];
            uint32_t h, l;
            split2(acc[mt][nt][0] + b0, acc[mt][nt][1] + b1, h, l);
            *(uint32_t*)&Oh[(size_t)r * E_ + cb] = h;
            *(uint32_t*)&Ol[(size_t)r * E_ + cb] = l;
            split2(acc[mt][nt][2] + b0, acc[mt][nt][3] + b1, h, l);
            *(uint32_t*)&Oh[(size_t)(r + 8) * E_ + cb] = h;
            *(uint32_t*)&Ol[(size_t)(r + 8) * E_ + cb] = l;
        }
    }
}

// ===========================================================================
// Kernel 2: per-warp register flash attention (unchanged from R8).
// ===========================================================================
#define AQ_HI 0
#define AQ_LO 10240
#define AK_HI 20480
#define AK_LO 33280
#define AV_HI 46080
#define AV_LO 58880
#define ATTN_SMEM 71680

__global__ __launch_bounds__(256)
void attn_kernel(const float* __restrict__ bias, float* __restrict__ out)
{
    extern __shared__ char smem[];
    const uint32_t sb = smem_u32(smem);

    const int n0 = blockIdx.x * 128;
    const int h  = blockIdx.y;
    const int b  = blockIdx.z;
    const int tid = threadIdx.x;
    const size_t basee = (size_t)(b * N_) * E_ + h * HD_;

    // ---- fill Q (128 rows x 32 d = 64 B/row), row stride 80B ----
    for (int idx = tid; idx < 512; idx += 256) {
        int r = idx >> 2, gc = idx & 3;
        size_t e = basee + (size_t)(n0 + r) * E_ + gc * 8;
        *(uint4*)(smem + AQ_HI + r * 80 + gc * 16) = *(const uint4*)&g_qh[e];
        *(uint4*)(smem + AQ_LO + r * 80 + gc * 16) = *(const uint4*)&g_ql[e];
    }
    // ---- fill K,V (160 rows; row r = key n0-31+r; pad rows = bias / zero) ----
    for (int idx = tid; idx < 640; idx += 256) {
        int r = idx >> 2, gc = idx & 3;
        int n = n0 - 31 + r;
        uint4 kh, kl, vh, vl;
        if ((unsigned)n < (unsigned)N_) {
            size_t e = basee + (size_t)n * E_ + gc * 8;
            kh = *(const uint4*)&g_kh[e];
            kl = *(const uint4*)&g_kl[e];
            vh = *(const uint4*)&g_vh[e];
            vl = *(const uint4*)&g_vl[e];
        } else if (n < 0) {
            float4 b0 = *(const float4*)&bias[h * HD_ + gc * 8];
            float4 b1 = *(const float4*)&bias[h * HD_ + gc * 8 + 4];
            uint32_t h0, l0, h1, l1, h2, l2, h3, l3;
            split2(b0.x, b0.y, h0, l0);
            split2(b0.z, b0.w, h1, l1);
            split2(b1.x, b1.y, h2, l2);
            split2(b1.z, b1.w, h3, l3);
            kh = make_uint4(h0, h1, h2, h3);
            kl = make_uint4(l0, l1, l2, l3);
            vh = kh; vl = kl;
        } else {
            kh = kl = vh = vl = make_uint4(0, 0, 0, 0);
        }
        uint32_t off = r * 80 + gc * 16;
        *(uint4*)(smem + AK_HI + off) = kh;
        *(uint4*)(smem + AK_LO + off) = kl;
        *(uint4*)(smem + AV_HI + off) = vh;
        *(uint4*)(smem + AV_LO + off) = vl;
    }
    __syncthreads();

    const int g    = tid >> 5;        // warp = 16-query group
    const int lane = tid & 31;
    const int sub = lane >> 3, r8 = lane & 7;
    const int j = lane >> 2;          // fragment row within 16-row tile
    const int cb2 = (lane & 3) * 2;   // fragment col pair base

    // ================= S = Q . K^T (16 x 48, k=32) =================
    float sf[6][4];
    #pragma unroll
    for (int f = 0; f < 6; f++)
        #pragma unroll
        for (int i = 0; i < 4; i++) sf[f][i] = 0.f;

    #pragma unroll
    for (int ks = 0; ks < 2; ks++) {
        int arow = g * 16 + (sub & 1) * 8 + r8;
        uint32_t aoff = arow * 80 + ks * 32 + (sub >> 1) * 16;
        uint32_t qh[4], ql[4];
        LDSM_X4(qh[0], qh[1], qh[2], qh[3], sb + AQ_HI + aoff);
        LDSM_X4(ql[0], ql[1], ql[2], ql[3], sb + AQ_LO + aoff);
        #pragma unroll
        for (int ng = 0; ng < 3; ng++) {
            int brow = g * 16 + ng * 16 + (sub >> 1) * 8 + r8;
            uint32_t boff = brow * 80 + ks * 32 + (sub & 1) * 16;
            uint32_t kh[4], kl[4];
            LDSM_X4(kh[0], kh[1], kh[2], kh[3], sb + AK_HI + boff);
            LDSM_X4(kl[0], kl[1], kl[2], kl[3], sb + AK_LO + boff);
            int f = ng * 2;
            MMA_BF16(sf[f],     qh, &kh[0]);
            MMA_BF16(sf[f + 1], qh, &kh[2]);
            MMA_BF16(sf[f],     qh, &kl[0]);
            MMA_BF16(sf[f + 1], qh, &kl[2]);
            MMA_BF16(sf[f],     ql, &kh[0]);
            MMA_BF16(sf[f + 1], ql, &kh[2]);
        }
    }

    // ================= mask + softmax in registers =================
    // Valid window for query row j: cols c with (c - j) in [0, 31].
    float mx0 = -1e30f, mx1 = -1e30f;
    #pragma unroll
    for (int f = 0; f < 6; f++) {
        int c = f * 8 + cb2;
        float s0 = sf[f][0] * SCALE_;
        float s1 = sf[f][1] * SCALE_;
        float s2 = sf[f][2] * SCALE_;
        float s3 = sf[f][3] * SCALE_;
        if ((unsigned)(c - j) >= 32u)           s0 = -1e30f;
        if ((unsigned)(c + 1 - j) >= 32u)       s1 = -1e30f;
        if ((unsigned)(c - (j + 8)) >= 32u)     s2 = -1e30f;
        if ((unsigned)(c + 1 - (j + 8)) >= 32u) s3 = -1e30f;
        sf[f][0] = s0; sf[f][1] = s1; sf[f][2] = s2; sf[f][3] = s3;
        mx0 = fmaxf(mx0, fmaxf(s0, s1));
        mx1 = fmaxf(mx1, fmaxf(s2, s3));
    }
    mx0 = fmaxf(mx0, __shfl_xor_sync(0xffffffffu, mx0, 1));
    mx0 = fmaxf(mx0, __shfl_xor_sync(0xffffffffu, mx0, 2));
    mx1 = fmaxf(mx1, __shfl_xor_sync(0xffffffffu, mx1, 1));
    mx1 = fmaxf(mx1, __shfl_xor_sync(0xffffffffu, mx1, 2));

    float sm0 = 0.f, sm1 = 0.f;
    #pragma unroll
    for (int f = 0; f < 6; f++) {
        float e0 = __expf(sf[f][0] - mx0);
        float e1 = __expf(sf[f][1] - mx0);
        float e2 = __expf(sf[f][2] - mx1);
        float e3 = __expf(sf[f][3] - mx1);
        sf[f][0] = e0; sf[f][1] = e1; sf[f][2] = e2; sf[f][3] = e3;
        sm0 += e0 + e1;
        sm1 += e2 + e3;
    }
    sm0 += __shfl_xor_sync(0xffffffffu, sm0, 1);
    sm0 += __shfl_xor_sync(0xffffffffu, sm0, 2);
    sm1 += __shfl_xor_sync(0xffffffffu, sm1, 1);
    sm1 += __shfl_xor_sync(0xffffffffu, sm1, 2);
    const float inv0 = 1.f / sm0;
    const float inv1 = 1.f / sm1;

    // ---- P (bf16 hi/lo) repacked directly into A-fragments ----
    uint32_t pah[3][4], pal[3][4];
    #pragma unroll
    for (int kf = 0; kf < 3; kf++) {
        int f0 = kf * 2, f1 = kf * 2 + 1;
        split2(sf[f0][0] * inv0, sf[f0][1] * inv0, pah[kf][0], pal[kf][0]);
        split2(sf[f0][2] * inv1, sf[f0][3] * inv1, pah[kf][1], pal[kf][1]);
        split2(sf[f1][0] * inv0, sf[f1][1] * inv0, pah[kf][2], pal[kf][2]);
        split2(sf[f1][2] * inv1, sf[f1][3] * inv1, pah[kf][3], pal[kf][3]);
    }

    // ================= O = P . V (16 x 32, k=48) =================
    float of[4][4];
    #pragma unroll
    for (int nf = 0; nf < 4; nf++)
        #pragma unroll
        for (int i = 0; i < 4; i++) of[nf][i] = 0.f;

    #pragma unroll
    for (int kf = 0; kf < 3; kf++) {
        #pragma unroll
        for (int dg = 0; dg < 2; dg++) {
            int vrow = g * 16 + kf * 16 + (sub & 1) * 8 + r8;
            uint32_t voff = vrow * 80 + dg * 32 + (sub >> 1) * 16;
            uint32_t vh[4], vl[4];
            LDSM_X4_T(vh[0], vh[1], vh[2], vh[3], sb + AV_HI + voff);
            LDSM_X4_T(vl[0], vl[1], vl[2], vl[3], sb + AV_LO + voff);
            int nf = dg * 2;
            MMA_BF16(of[nf],     pah[kf], &vh[0]);
            MMA_BF16(of[nf + 1], pah[kf], &vh[2]);
            MMA_BF16(of[nf],     pah[kf], &vl[0]);
            MMA_BF16(of[nf + 1], pah[kf], &vl[2]);
            MMA_BF16(of[nf],     pal[kf], &vh[0]);
            MMA_BF16(of[nf + 1], pal[kf], &vh[2]);
        }
    }

    // ---- store output ----
    #pragma unroll
    for (int nf = 0; nf < 4; nf++) {
        int d = nf * 8 + cb2;
        int n = n0 + g * 16 + j;
        float2 o0 = { of[nf][0], of[nf][1] };
        float2 o1 = { of[nf][2], of[nf][3] };
        *(float2*)&out[basee + (size_t)n * E_ + d]       = o0;
        *(float2*)&out[basee + (size_t)(n + 8) * E_ + d] = o1;
    }
}

// ===========================================================================
extern "C" void kernel_launch(void* const* d_in, const int* in_sizes, int n_in,
                              void* d_out, int out_size)
{
    const float* q = (const float*)d_in[0];
    const float* k = (const float*)d_in[1];
    const float* v = (const float*)d_in[2];
    const float* W = (const float*)d_in[3];
    const float* b = (const float*)d_in[4];
    float* out = (float*)d_out;

    cudaFuncSetAttribute(proj_mma_kernel,
                         cudaFuncAttributeMaxDynamicSharedMemorySize, PROJ_SMEM);
    cudaFuncSetAttribute(attn_kernel,
                         cudaFuncAttributeMaxDynamicSharedMemorySize, ATTN_SMEM);

    const int conv_threads = (3 * M_TOT * E_ + WT) / 4;
    convert_kernel<<<(conv_threads + 255) / 256, 256>>>(q, k, v, W);

    dim3 gProj(4, 64, 3);
    proj_mma_kernel<<<gProj, 256, PROJ_SMEM>>>(b);

    dim3 gAttn(N_ / 128, H_, B_);
    attn_kernel<<<gAttn, 256, ATTN_SMEM>>>(b, out);
}